// round 8
// baseline (speedup 1.0000x reference)
#include <cuda_runtime.h>
#include <cstdint>

// Problem dims
#define NIMG 32
#define CCH 16
#define HH 224
#define WW 224
#define HWSZ (HH*WW)          // 50176
#define NPIX (NIMG*HWSZ)      // 1,605,632 pixels
#define TOTAL (NIMG*CCH*HWSZ) // 25,690,112 elements

// Conv tiling: 16x16 pixel tile, 256 threads (8 warps), implicit GEMM via
// mma.sync m16n8k32 s8: M=16 oc, N=8 px per mma, K=160 (16ch x 10 taps, tap9=0)
#define TH 16
#define TW 16
#define GX 14
#define GY 14

// ---------------- scratch (device globals: no allocations allowed) ----------
__device__ unsigned           g_maxbits;     // max|x| as float bits (all >= 0)
__device__ float              g_stepw;       // weight quant step
__device__ float              g_invx;        // 1 / activation step (precomputed once)
__device__ int4               g_wq[16*9];    // packed int8 weights [oc][tap]
__device__ int                g_acc[TOTAL];  // raw conv accumulators (int32, NCHW)
__device__ unsigned long long g_sumI[16];    // exact global sum of acc
__device__ unsigned long long g_sumQ[16];    // exact global sum of acc^2
__device__ float              g_scale[16];   // fused BN scale (incl. stepx*stepw)
__device__ float              g_bias[16];    // fused BN bias

// ---------------- mma wrapper ----------------------------------------------
__device__ __forceinline__ void mma_s8(int* d, int a0, int a1, int a2, int a3,
                                       int b0, int b1) {
    asm volatile(
        "mma.sync.aligned.m16n8k32.row.col.s32.s8.s8.s32 "
        "{%0,%1,%2,%3},{%4,%5,%6,%7},{%8,%9},{%0,%1,%2,%3};"
        : "+r"(d[0]), "+r"(d[1]), "+r"(d[2]), "+r"(d[3])
        : "r"(a0), "r"(a1), "r"(a2), "r"(a3), "r"(b0), "r"(b1));
}

// ---------------- k_init: reset + weight max + weight quantize/pack ---------
__global__ void k_init(const float* __restrict__ w) {
    __shared__ float red[256];
    __shared__ float s_stepw;
    int t = threadIdx.x;
    if (t == 0) g_maxbits = 0u;
    if (t < 16) { g_sumI[t] = 0ull; g_sumQ[t] = 0ull; }
    float m = 0.f;
    for (int i = t; i < 16*16*9; i += 256) m = fmaxf(m, fabsf(w[i]));
    red[t] = m; __syncthreads();
    for (int s = 128; s; s >>= 1) {
        if (t < s) red[t] = fmaxf(red[t], red[t+s]);
        __syncthreads();
    }
    if (t == 0) {
        float sw = __fdiv_rn(red[0], 127.0f);
        g_stepw = sw; s_stepw = sw;
    }
    __syncthreads();
    float sw = s_stepw;
    if (t < 144) {
        int oc = t / 9, tap = t % 9;
        int vals[4];
        #pragma unroll
        for (int g = 0; g < 4; ++g) {
            int packed = 0;
            #pragma unroll
            for (int b = 0; b < 4; ++b) {
                int c = g*4 + b;
                float v = w[(oc*16 + c)*9 + tap];
                float q = rintf(__fdiv_rn(v, sw));
                q = fminf(fmaxf(q, -127.f), 127.f);
                int qi = (int)q;
                packed |= (qi & 0xFF) << (8*b);
            }
            vals[g] = packed;
        }
        g_wq[oc*9 + tap] = make_int4(vals[0], vals[1], vals[2], vals[3]);
    }
}

// ---------------- k_xmax: global max|x| ------------------------------------
__global__ void k_xmax(const float4* __restrict__ x) {
    float m = 0.f;
    int stride = gridDim.x * blockDim.x;
    for (int i = blockIdx.x*blockDim.x + threadIdx.x; i < TOTAL/4; i += stride) {
        float4 v = x[i];
        m = fmaxf(m, fmaxf(fmaxf(fabsf(v.x), fabsf(v.y)), fmaxf(fabsf(v.z), fabsf(v.w))));
    }
    #pragma unroll
    for (int off = 16; off; off >>= 1)
        m = fmaxf(m, __shfl_xor_sync(0xFFFFFFFFu, m, off));
    __shared__ float red[8];
    int lane = threadIdx.x & 31, wp = threadIdx.x >> 5;
    if (lane == 0) red[wp] = m;
    __syncthreads();
    if (threadIdx.x == 0) {
        float mm = red[0];
        #pragma unroll
        for (int i = 1; i < 8; ++i) mm = fmaxf(mm, red[i]);
        atomicMax(&g_maxbits, __float_as_uint(mm));
    }
}

// ---------------- k_prep: one-time scalar prep (activation inv step) --------
__global__ void k_prep() {
    if (threadIdx.x == 0) {
        float sx = __fdiv_rn(__uint_as_float(g_maxbits), 127.0f);
        g_invx = __fdiv_rn(1.0f, sx);
    }
}

// ---------------- conv: fused quantize + tensor-core implicit GEMM ----------
// Loads raw fp32 halo, quantizes+packs into smem, runs IMMA, stores raw acc,
// and accumulates exact global BN statistics.
__global__ void __launch_bounds__(256, 4) k_conv(const float* __restrict__ x) {
    __shared__ int4 s_x[18][18];        // halo tile, pixel-major int8x16, 5184 B
    __shared__ int4 s_w[160];           // [oc][tap0..9], 2560 B
    __shared__ int       s_I[8][16];
    __shared__ long long s_Q[8][16];

    int t = threadIdx.x;
    int n = blockIdx.z;
    int h0 = blockIdx.y * TH, w0 = blockIdx.x * TW;

    // fused halo load + quantize (zero padded). i = c*324 + r*18 + cc
    {
        float inv = g_invx;
        const float* xn = x + (size_t)n*(CCH*HWSZ);
        char* sxb = (char*)s_x;
        #pragma unroll 3
        for (int i = t; i < 16*324; i += 256) {
            int c = i / 324, rem = i - c*324;
            int r = rem / 18, cc = rem - r*18;
            int gh = h0 - 1 + r, gw = w0 - 1 + cc;
            float f = 0.f;
            if ((unsigned)gh < (unsigned)HH && (unsigned)gw < (unsigned)WW)
                f = __ldg(xn + (size_t)c*HWSZ + gh*WW + gw);
            float q = rintf(f * inv);
            q = fminf(fmaxf(q, -127.f), 127.f);
            sxb[(r*18 + cc)*16 + c] = (char)(int)q;
        }
    }
    if (t < 160) {
        int oc = t / 10, tap = t - oc*10;
        s_w[t] = (tap < 9) ? g_wq[oc*9 + tap] : make_int4(0,0,0,0);
    }
    __syncthreads();

    int w = t >> 5, l = t & 31;
    int g4 = l >> 2, q = l & 3;          // A/C row group, K word index
    const int* swi = (const int*)s_w;

    int acc[4][4];
    #pragma unroll
    for (int tt = 0; tt < 4; ++tt)
        #pragma unroll
        for (int j = 0; j < 4; ++j) acc[tt][j] = 0;

    #pragma unroll
    for (int kc = 0; kc < 5; ++kc) {
        const int tap0 = 2*kc, tap1 = 2*kc + 1;
        const int dy0 = tap0/3,                  dx0 = tap0%3;
        const int dy1 = (tap1 < 9) ? tap1/3 : 2, dx1 = (tap1 < 9) ? tap1%3 : 2;
        int a0 = swi[(g4*10     + tap0)*4 + q];
        int a1 = swi[((g4+8)*10 + tap0)*4 + q];
        int a2 = swi[(g4*10     + tap1)*4 + q];
        int a3 = swi[((g4+8)*10 + tap1)*4 + q];
        #pragma unroll
        for (int tt = 0; tt < 4; ++tt) {
            int r0 = 2*w + (tt & 1), c0 = 8*(tt >> 1);
            const int* bp0 = (const int*)&s_x[r0 + dy0][c0 + dx0];
            const int* bp1 = (const int*)&s_x[r0 + dy1][c0 + dx1];
            mma_s8(acc[tt], a0, a1, a2, a3, bp0[l], bp1[l]);
        }
    }

    // store raw accumulators (int2 per oc-half, coalesced per quad)
    #pragma unroll
    for (int tt = 0; tt < 4; ++tt) {
        int r0 = 2*w + (tt & 1), c0 = 8*(tt >> 1);
        size_t ob = (size_t)n*CCH*HWSZ + (size_t)(h0 + r0)*WW + (w0 + c0 + 2*q);
        *(int2*)(g_acc + ob + (size_t)g4*HWSZ)     = make_int2(acc[tt][0], acc[tt][1]);
        *(int2*)(g_acc + ob + (size_t)(g4+8)*HWSZ) = make_int2(acc[tt][2], acc[tt][3]);
    }

    // exact per-channel integer stats
    int sl = 0, sh = 0;
    long long ql = 0, qh = 0;
    #pragma unroll
    for (int tt = 0; tt < 4; ++tt) {
        sl += acc[tt][0] + acc[tt][1];
        sh += acc[tt][2] + acc[tt][3];
        ql += (long long)acc[tt][0]*acc[tt][0] + (long long)acc[tt][1]*acc[tt][1];
        qh += (long long)acc[tt][2]*acc[tt][2] + (long long)acc[tt][3]*acc[tt][3];
    }
    sl += __shfl_xor_sync(0xFFFFFFFFu, sl, 1);
    sl += __shfl_xor_sync(0xFFFFFFFFu, sl, 2);
    sh += __shfl_xor_sync(0xFFFFFFFFu, sh, 1);
    sh += __shfl_xor_sync(0xFFFFFFFFu, sh, 2);
    ql += __shfl_xor_sync(0xFFFFFFFFu, ql, 1);
    ql += __shfl_xor_sync(0xFFFFFFFFu, ql, 2);
    qh += __shfl_xor_sync(0xFFFFFFFFu, qh, 1);
    qh += __shfl_xor_sync(0xFFFFFFFFu, qh, 2);
    if (q == 0) {
        s_I[w][g4]     = sl;  s_Q[w][g4]     = ql;
        s_I[w][g4 + 8] = sh;  s_Q[w][g4 + 8] = qh;
    }
    __syncthreads();
    if (t < 16) {
        long long ti = 0, tq = 0;
        #pragma unroll
        for (int wp = 0; wp < 8; ++wp) {
            ti += (long long)s_I[wp][t];
            tq += s_Q[wp][t];
        }
        atomicAdd(&g_sumI[t], (unsigned long long)ti);
        atomicAdd(&g_sumQ[t], (unsigned long long)tq);
    }
}

// ---------------- k_fin: compute BN affine from exact sums ------------------
__global__ void k_fin(const float* __restrict__ gamma, const float* __restrict__ beta) {
    int t = threadIdx.x;
    if (t < 16) {
        double stepx = (double)__fdiv_rn(__uint_as_float(g_maxbits), 127.0f);
        double sc = stepx * (double)g_stepw;      // y = sc * acc (exact)
        double M = (double)NPIX;
        double sumI = (double)(long long)g_sumI[t];
        double sumQ = (double)(long long)g_sumQ[t];
        double mean = sc * sumI / M;
        double ey2  = sc * sc * sumQ / M;
        double var  = ey2 - mean*mean;
        double inv  = (double)gamma[t] / sqrt(var + 1e-5);
        g_scale[t] = (float)(sc * inv);
        g_bias[t]  = (float)((double)beta[t] - mean * inv);
    }
}

// ---------------- k_epi: memory-bound affine epilogue -----------------------
__global__ void k_epi(float* __restrict__ out) {
    int plane = blockIdx.y;              // n*16 + c
    int c = plane & 15;
    float sc = g_scale[c], bi = g_bias[c];
    int i = blockIdx.x * blockDim.x + threadIdx.x;
    size_t base = (size_t)plane * HWSZ + (size_t)i * 4;
    int4 a = *(const int4*)(g_acc + base);
    float4 v;
    v.x = fminf(fmaxf(fmaf((float)a.x, sc, bi), 0.f), 6.f);
    v.y = fminf(fmaxf(fmaf((float)a.y, sc, bi), 0.f), 6.f);
    v.z = fminf(fmaxf(fmaf((float)a.z, sc, bi), 0.f), 6.f);
    v.w = fminf(fmaxf(fmaf((float)a.w, sc, bi), 0.f), 6.f);
    *(float4*)(out + base) = v;
}

// ---------------- launch ----------------------------------------------------
extern "C" void kernel_launch(void* const* d_in, const int* in_sizes, int n_in,
                              void* d_out, int out_size) {
    const float* x     = (const float*)d_in[0];
    const float* wgt   = (const float*)d_in[1];
    const float* gamma = (const float*)d_in[2];
    const float* beta  = (const float*)d_in[3];
    float* out = (float*)d_out;

    k_init<<<1, 256>>>(wgt);
    k_xmax<<<1184, 256>>>((const float4*)x);
    k_prep<<<1, 32>>>();
    dim3 g(GX, GY, NIMG);
    k_conv<<<g, 256>>>(x);
    k_fin<<<1, 32>>>(gamma, beta);
    dim3 ge(HWSZ/4/256, NIMG*CCH);       // (49, 512)
    k_epi<<<ge, 256>>>(out);
}